// round 10
// baseline (speedup 1.0000x reference)
#include <cuda_runtime.h>
#include <stdint.h>

#define N_BOX 32768
#define C_CLS 81
#define K_TOP 4096
#define SCORE_T 0.05f
#define NMS_T 0.5f
#define IMG_W 1333.0f
#define IMG_H 800.0f
#define CLS_OFF 4096.0f

#define CAND_MAX (N_BOX * 20)   // provably <=19 candidates/row (probs sum to 1)
#define SEL_MAX 16384

// p in (0.05, 1.0]  =>  float top-16 bits in [0x3D4C, 0x3F80]
#define HIST_LO 0x3D4C
#define HIST_N  565

#define NMS_CAP 256   // max rows per class (mean ~51, 29-sigma safe)

// ---- device state. Invariant: every counter/accumulator is zero on entry to
// each kernel_launch call (zero-init at load; consume-then-reset thereafter).
__device__ unsigned long long g_cand[CAND_MAX];
__device__ int g_cnt;
__device__ unsigned int g_hist[HIST_N];
__device__ int g_cutBucket;
__device__ unsigned long long g_sel[SEL_MAX];
__device__ int g_selCnt;

__device__ float g_bk[K_TOP][4];
__device__ float g_boff[K_TOP][4];
__device__ float g_area[K_TOP];
__device__ float g_val[K_TOP];
__device__ int   g_label[K_TOP];

__device__ unsigned long long g_removed[64];

// xor-butterfly tree sum — all lanes end with identical bits (VALIDATED)
__device__ __forceinline__ float btree_add(float v) {
    #pragma unroll
    for (int o = 16; o; o >>= 1) v = __fadd_rn(v, __shfl_xor_sync(0xFFFFFFFFu, v, o));
    return v;
}

// one warp per row — bitwise model of the Triton/MLIR normalization emitter
// (VALIDATED round 6: rel_err 9.3e-12 — arithmetic is FROZEN)
__global__ void k_softmax(const float* __restrict__ x) {
    int warp = (blockIdx.x * blockDim.x + threadIdx.x) >> 5;
    int lane = threadIdx.x & 31;
    if (warp >= N_BOX) return;
    const float* row = x + (size_t)warp * C_CLS;

    float v0 = row[lane];
    float v1 = row[lane + 32];
    float v2 = (lane < 17) ? row[lane + 64] : -1e30f;

    float m = fmaxf(fmaxf(v0, v1), v2);
    #pragma unroll
    for (int o = 16; o; o >>= 1) m = fmaxf(m, __shfl_xor_sync(0xFFFFFFFFu, m, o));

    float e0 = expf(__fsub_rn(v0, m));
    float e1 = expf(__fsub_rn(v1, m));
    float e2 = (lane < 17) ? expf(__fsub_rn(v2, m)) : 0.0f;

    float B0 = btree_add(e0);
    float B1 = btree_add(e1);
    float B2 = btree_add(e2);
    float s = __fadd_rn(__fadd_rn(B0, B2), B1);

    float p0 = __fdiv_rn(e0, s);
    float p1 = __fdiv_rn(e1, s);
    float p2 = __fdiv_rn(e2, s);

    bool val0 = (lane != 0) && (p0 > SCORE_T);
    bool val1 = (p1 > SCORE_T);
    bool val2 = (lane < 17) && (p2 > SCORE_T);

    unsigned bal0 = __ballot_sync(0xFFFFFFFFu, val0);
    unsigned bal1 = __ballot_sync(0xFFFFFFFFu, val1);
    unsigned bal2 = __ballot_sync(0xFFFFFFFFu, val2);
    int n0 = __popc(bal0), n1 = __popc(bal1), n2 = __popc(bal2);
    int tot = n0 + n1 + n2;
    int base = 0;
    if (lane == 0 && tot) base = atomicAdd(&g_cnt, tot);
    base = __shfl_sync(0xFFFFFFFFu, base, 0);
    unsigned lmask = (1u << lane) - 1u;
    unsigned rowbase = (unsigned)warp * C_CLS;

    if (val0) {
        unsigned vb = __float_as_uint(p0);
        g_cand[base + __popc(bal0 & lmask)] =
            ((unsigned long long)vb << 32) | (0xFFFFFFFFu - (rowbase + lane));
        atomicAdd(&g_hist[(vb >> 16) - HIST_LO], 1u);
    }
    if (val1) {
        unsigned vb = __float_as_uint(p1);
        g_cand[base + n0 + __popc(bal1 & lmask)] =
            ((unsigned long long)vb << 32) | (0xFFFFFFFFu - (rowbase + lane + 32));
        atomicAdd(&g_hist[(vb >> 16) - HIST_LO], 1u);
    }
    if (val2) {
        unsigned vb = __float_as_uint(p2);
        g_cand[base + n0 + n1 + __popc(bal2 & lmask)] =
            ((unsigned long long)vb << 32) | (0xFFFFFFFFu - (rowbase + lane + 64));
        atomicAdd(&g_hist[(vb >> 16) - HIST_LO], 1u);
    }
}

// find cut bucket; consume-then-reset g_hist; zero selCnt for k_compact
__global__ void k_findcut() {
    __shared__ unsigned int h[HIST_N];
    int t = threadIdx.x;
    if (t < HIST_N) { h[t] = g_hist[t]; g_hist[t] = 0u; }
    if (t == 0) g_selCnt = 0;
    __syncthreads();
    if (t == 0) {
        unsigned int acc = 0;
        int b = HIST_N - 1;
        for (; b >= 0; b--) {
            acc += h[b];
            if (acc >= K_TOP) break;
        }
        g_cutBucket = (b < 0) ? 0 : b;
    }
}

__global__ void k_compact() {
    int cnt = g_cnt;
    int cut = g_cutBucket;
    int stride = gridDim.x * blockDim.x;
    for (int t = blockIdx.x * blockDim.x + threadIdx.x; t < cnt; t += stride) {
        unsigned long long key = g_cand[t];
        if ((int)((unsigned)(key >> 48) - HIST_LO) >= cut) {
            int pos = atomicAdd(&g_selCnt, 1);
            if (pos < SEL_MAX) g_sel[pos] = key;
        }
    }
}

// fused exact rank (descending, keys unique) + decode/scatter into final slot;
// also resets g_cnt (its last reader, k_compact, already ran)
__global__ void k_rankscatter(const float* __restrict__ boxes) {
    __shared__ unsigned long long tile[256];
    if (blockIdx.x == 0 && threadIdx.x == 0) g_cnt = 0;
    int m = g_selCnt; if (m > SEL_MAX) m = SEL_MAX;
    int i0 = blockIdx.x * 256;
    if (i0 >= m) return;                    // uniform per block
    int i = i0 + threadIdx.x;
    unsigned long long key = (i < m) ? g_sel[i] : 0ull;
    int cnt = 0;
    int ntile = (m + 255) >> 8;
    for (int tb = 0; tb < ntile; tb++) {
        int jt = tb * 256 + threadIdx.x;
        __syncthreads();
        tile[threadIdx.x] = (jt < m) ? g_sel[jt] : 0ull;
        __syncthreads();
        int lim = m - tb * 256; if (lim > 256) lim = 256;
        #pragma unroll 8
        for (int j = 0; j < lim; j++) cnt += (tile[j] > key);
    }
    if (i >= m || cnt >= K_TOP) return;
    int r = cnt;
    unsigned idx = 0xFFFFFFFFu - (unsigned)(key & 0xFFFFFFFFull);
    float val = __uint_as_float((unsigned)(key >> 32));
    int bi = (int)(idx / C_CLS);
    int lb = (int)(idx % C_CLS);
    float x1 = fminf(fmaxf(boxes[bi * 4 + 0], 0.0f), IMG_W - 1.0f);
    float y1 = fminf(fmaxf(boxes[bi * 4 + 1], 0.0f), IMG_H - 1.0f);
    float x2 = fminf(fmaxf(boxes[bi * 4 + 2], 0.0f), IMG_W - 1.0f);
    float y2 = fminf(fmaxf(boxes[bi * 4 + 3], 0.0f), IMG_H - 1.0f);
    g_bk[r][0] = x1; g_bk[r][1] = y1; g_bk[r][2] = x2; g_bk[r][3] = y2;
    g_val[r] = val; g_label[r] = lb;
    float off = __fmul_rn((float)lb, CLS_OFF);
    float ox1 = __fadd_rn(x1, off), oy1 = __fadd_rn(y1, off);
    float ox2 = __fadd_rn(x2, off), oy2 = __fadd_rn(y2, off);
    g_boff[r][0] = ox1; g_boff[r][1] = oy1; g_boff[r][2] = ox2; g_boff[r][3] = oy2;
    g_area[r] = __fmul_rn(__fsub_rn(ox2, ox1), __fsub_rn(oy2, oy1));
}

// Per-class NMS: one warp per class. Cross-class IoU is exactly 0 (class offset
// 4096 exceeds the clipped image extent), so the global greedy recurrence
// decomposes into independent per-class chains over rows in ascending rank.
__global__ void k_nms() {
    __shared__ int s_rows[NMS_CAP];
    __shared__ float s_box[NMS_CAP][4];
    __shared__ float s_area[NMS_CAP];
    __shared__ unsigned long long s_sup[NMS_CAP][4];
    __shared__ unsigned long long s_rm[4];

    int c = blockIdx.x + 1;          // classes 1..80
    int lane = threadIdx.x;          // 32 threads
    unsigned lmask = (1u << lane) - 1u;

    // gather this class's rows in ascending rank order
    int k = 0;
    for (int base = 0; base < K_TOP; base += 32) {
        int r = base + lane;
        bool mt = (g_label[r] == c) && (g_val[r] > 0.0f);
        unsigned bal = __ballot_sync(0xFFFFFFFFu, mt);
        if (mt) {
            int pos = k + __popc(bal & lmask);
            if (pos < NMS_CAP) s_rows[pos] = r;
        }
        k += __popc(bal);
    }
    if (k > NMS_CAP) k = NMS_CAP;
    if (k <= 1) return;

    for (int i = lane; i < k; i += 32) {
        int r = s_rows[i];
        s_box[i][0] = g_boff[r][0]; s_box[i][1] = g_boff[r][1];
        s_box[i][2] = g_boff[r][2]; s_box[i][3] = g_boff[r][3];
        s_area[i] = g_area[r];
    }
    __syncwarp();

    // suppression rows: sup[i] bits j>i with IoU>0.5 (identical _rn sequence)
    for (int i = lane; i < k; i += 32) {
        float x1 = s_box[i][0], y1 = s_box[i][1], x2 = s_box[i][2], y2 = s_box[i][3];
        float ai = s_area[i];
        unsigned long long w0 = 0, w1 = 0, w2 = 0, w3 = 0;
        for (int j = i + 1; j < k; j++) {
            float iw = fmaxf(__fsub_rn(fminf(x2, s_box[j][2]), fmaxf(x1, s_box[j][0])), 0.0f);
            float ih = fmaxf(__fsub_rn(fminf(y2, s_box[j][3]), fmaxf(y1, s_box[j][1])), 0.0f);
            float inter = __fmul_rn(iw, ih);
            float denom = __fadd_rn(__fsub_rn(__fadd_rn(ai, s_area[j]), inter), 1e-9f);
            if (__fdiv_rn(inter, denom) > NMS_T) {
                unsigned long long b = 1ull << (j & 63);
                switch (j >> 6) { case 0: w0 |= b; break; case 1: w1 |= b; break;
                                  case 2: w2 |= b; break; default: w3 |= b; break; }
            }
        }
        s_sup[i][0] = w0; s_sup[i][1] = w1; s_sup[i][2] = w2; s_sup[i][3] = w3;
    }
    __syncwarp();

    if (lane == 0) {
        unsigned long long r0 = 0, r1 = 0, r2 = 0, r3 = 0;
        for (int i = 0; i < k; i++) {
            unsigned long long rw = (i < 64) ? r0 : (i < 128) ? r1 : (i < 192) ? r2 : r3;
            if (!((rw >> (i & 63)) & 1ull)) {
                r0 |= s_sup[i][0]; r1 |= s_sup[i][1];
                r2 |= s_sup[i][2]; r3 |= s_sup[i][3];
            }
        }
        s_rm[0] = r0; s_rm[1] = r1; s_rm[2] = r2; s_rm[3] = r3;
    }
    __syncwarp();

    if (lane < 4) {
        unsigned long long bits = s_rm[lane];
        while (bits) {
            int b = __ffsll((long long)bits) - 1;
            bits &= bits - 1ull;
            int li = lane * 64 + b;
            if (li < k) {
                int r = s_rows[li];
                atomicOr(&g_removed[r >> 6], 1ull << (r & 63));
            }
        }
    }
}

// single block: snapshot g_removed, reset it (for the next call), emit output
// layout (float32, concatenated): dets[4096*5], labels[4096], keep[4096]
__global__ void k_out(float* __restrict__ out, int out_size) {
    __shared__ unsigned long long s_rm[64];
    int t = threadIdx.x;
    if (t < 64) s_rm[t] = g_removed[t];
    __syncthreads();
    if (t < 64) g_removed[t] = 0ull;

    for (int o = t; o < out_size; o += blockDim.x) {
        float v = 0.0f;
        if (o < K_TOP * 5) {
            int r = o / 5, c = o - r * 5;
            bool keep = !((s_rm[r >> 6] >> (r & 63)) & 1ull) && (g_val[r] > 0.0f);
            if (keep) v = (c < 4) ? g_bk[r][c] : g_val[r];
        } else if (o < K_TOP * 6) {
            v = (float)g_label[o - K_TOP * 5];
        } else if (o < K_TOP * 7) {
            int r = o - K_TOP * 6;
            bool keep = !((s_rm[r >> 6] >> (r & 63)) & 1ull) && (g_val[r] > 0.0f);
            v = keep ? 1.0f : 0.0f;
        }
        out[o] = v;
    }
}

extern "C" void kernel_launch(void* const* d_in, const int* in_sizes, int n_in,
                              void* d_out, int out_size) {
    const float* x     = (const float*)d_in[0];
    const float* boxes = (const float*)d_in[1];
    float* out = (float*)d_out;

    k_softmax<<<N_BOX / 8, 256>>>(x);
    k_findcut<<<1, 576>>>();
    k_compact<<<512, 256>>>();
    k_rankscatter<<<SEL_MAX / 256, 256>>>(boxes);
    k_nms<<<C_CLS - 1, 32>>>();
    k_out<<<1, 1024>>>(out, out_size);
}

// round 11
// speedup vs baseline: 1.3798x; 1.3798x over previous
#include <cuda_runtime.h>
#include <stdint.h>

#define N_BOX 32768
#define C_CLS 81
#define K_TOP 4096
#define SCORE_T 0.05f
#define NMS_T 0.5f
#define IMG_W 1333.0f
#define IMG_H 800.0f
#define CLS_OFF 4096.0f

#define CAND_MAX (N_BOX * 20)   // provably <=19 candidates/row (probs sum to 1)
#define SEL_MAX 16384

// p in (0.05, 1.0]  =>  float top-16 bits in [0x3D4C, 0x3F80]
#define HIST_LO 0x3D4C
#define HIST_N  565

#define NMS_CAP 256   // max rows per class (mean ~51)

// ---- device state. Invariant: every counter/accumulator is zero on entry to
// each kernel_launch call (zero-init at load; consume-then-reset / pre-zeroed
// by an earlier kernel in the same call).
__device__ unsigned long long g_cand[CAND_MAX];
__device__ int g_cnt;
__device__ unsigned int g_hist[HIST_N];
__device__ int g_cutBucket;
__device__ unsigned long long g_sel[SEL_MAX];
__device__ int g_selCnt;
__device__ int g_rank[SEL_MAX];

__device__ int g_clsCnt[C_CLS];
__device__ int g_clsRows[C_CLS * NMS_CAP];

__device__ float g_bk[K_TOP][4];
__device__ float g_boff[K_TOP][4];
__device__ float g_area[K_TOP];
__device__ float g_val[K_TOP];
__device__ int   g_label[K_TOP];

__device__ unsigned long long g_removed[64];

// xor-butterfly tree sum — all lanes end with identical bits (VALIDATED)
__device__ __forceinline__ float btree_add(float v) {
    #pragma unroll
    for (int o = 16; o; o >>= 1) v = __fadd_rn(v, __shfl_xor_sync(0xFFFFFFFFu, v, o));
    return v;
}

// one warp per row — bitwise model of the Triton/MLIR normalization emitter
// (VALIDATED round 6: rel_err 9.3e-12 — arithmetic is FROZEN)
__global__ void k_softmax(const float* __restrict__ x) {
    int warp = (blockIdx.x * blockDim.x + threadIdx.x) >> 5;
    int lane = threadIdx.x & 31;
    if (warp >= N_BOX) return;
    const float* row = x + (size_t)warp * C_CLS;

    float v0 = row[lane];
    float v1 = row[lane + 32];
    float v2 = (lane < 17) ? row[lane + 64] : -1e30f;

    float m = fmaxf(fmaxf(v0, v1), v2);
    #pragma unroll
    for (int o = 16; o; o >>= 1) m = fmaxf(m, __shfl_xor_sync(0xFFFFFFFFu, m, o));

    float e0 = expf(__fsub_rn(v0, m));
    float e1 = expf(__fsub_rn(v1, m));
    float e2 = (lane < 17) ? expf(__fsub_rn(v2, m)) : 0.0f;

    float B0 = btree_add(e0);
    float B1 = btree_add(e1);
    float B2 = btree_add(e2);
    float s = __fadd_rn(__fadd_rn(B0, B2), B1);

    float p0 = __fdiv_rn(e0, s);
    float p1 = __fdiv_rn(e1, s);
    float p2 = __fdiv_rn(e2, s);

    bool val0 = (lane != 0) && (p0 > SCORE_T);
    bool val1 = (p1 > SCORE_T);
    bool val2 = (lane < 17) && (p2 > SCORE_T);

    unsigned bal0 = __ballot_sync(0xFFFFFFFFu, val0);
    unsigned bal1 = __ballot_sync(0xFFFFFFFFu, val1);
    unsigned bal2 = __ballot_sync(0xFFFFFFFFu, val2);
    int n0 = __popc(bal0), n1 = __popc(bal1), n2 = __popc(bal2);
    int tot = n0 + n1 + n2;
    int base = 0;
    if (lane == 0 && tot) base = atomicAdd(&g_cnt, tot);
    base = __shfl_sync(0xFFFFFFFFu, base, 0);
    unsigned lmask = (1u << lane) - 1u;
    unsigned rowbase = (unsigned)warp * C_CLS;

    if (val0) {
        unsigned vb = __float_as_uint(p0);
        g_cand[base + __popc(bal0 & lmask)] =
            ((unsigned long long)vb << 32) | (0xFFFFFFFFu - (rowbase + lane));
        atomicAdd(&g_hist[(vb >> 16) - HIST_LO], 1u);
    }
    if (val1) {
        unsigned vb = __float_as_uint(p1);
        g_cand[base + n0 + __popc(bal1 & lmask)] =
            ((unsigned long long)vb << 32) | (0xFFFFFFFFu - (rowbase + lane + 32));
        atomicAdd(&g_hist[(vb >> 16) - HIST_LO], 1u);
    }
    if (val2) {
        unsigned vb = __float_as_uint(p2);
        g_cand[base + n0 + n1 + __popc(bal2 & lmask)] =
            ((unsigned long long)vb << 32) | (0xFFFFFFFFu - (rowbase + lane + 64));
        atomicAdd(&g_hist[(vb >> 16) - HIST_LO], 1u);
    }
}

// find cut bucket; consume-then-reset g_hist; pre-zero rank/selCnt/clsCnt
__global__ void k_findcut() {
    __shared__ unsigned int h[HIST_N];
    int t = threadIdx.x;
    if (t < HIST_N) { h[t] = g_hist[t]; g_hist[t] = 0u; }
    if (t == 0) g_selCnt = 0;
    if (t < C_CLS) g_clsCnt[t] = 0;
    for (int i = t; i < SEL_MAX; i += 1024) g_rank[i] = 0;
    __syncthreads();
    if (t == 0) {
        unsigned int acc = 0;
        int b = HIST_N - 1;
        for (; b >= 0; b--) {
            acc += h[b];
            if (acc >= K_TOP) break;
        }
        g_cutBucket = (b < 0) ? 0 : b;
    }
}

__global__ void k_compact() {
    int cnt = g_cnt;
    int cut = g_cutBucket;
    int stride = gridDim.x * blockDim.x;
    for (int t = blockIdx.x * blockDim.x + threadIdx.x; t < cnt; t += stride) {
        unsigned long long key = g_cand[t];
        if ((int)((unsigned)(key >> 48) - HIST_LO) >= cut) {
            int pos = atomicAdd(&g_selCnt, 1);
            if (pos < SEL_MAX) g_sel[pos] = key;
        }
    }
}

// exact dense rank (descending, keys unique): one 256x256 tile per block —
// full parallelism across ~324 active CTAs, partial counts via atomicAdd
__global__ void k_rank() {
    __shared__ unsigned long long tile[256];
    int m = g_selCnt; if (m > SEL_MAX) m = SEL_MAX;
    int i0 = blockIdx.x * 256, j0 = blockIdx.y * 256;
    if (i0 >= m || j0 >= m) return;                 // uniform per block
    int jt = j0 + threadIdx.x;
    tile[threadIdx.x] = (jt < m) ? g_sel[jt] : 0ull; // pad keys 0 < any real key
    __syncthreads();
    int i = i0 + threadIdx.x;
    if (i >= m) return;
    unsigned long long key = g_sel[i];
    int lim = m - j0; if (lim > 256) lim = 256;
    int cnt = 0;
    #pragma unroll 8
    for (int j = 0; j < lim; j++) cnt += (tile[j] > key);
    if (cnt) atomicAdd(&g_rank[i], cnt);
}

// decode each selected key into its final sorted slot + build per-class lists;
// also resets g_cnt (its last reader, k_compact, already ran)
__global__ void k_scatter(const float* __restrict__ boxes) {
    if (blockIdx.x == 0 && threadIdx.x == 0) g_cnt = 0;
    int m = g_selCnt; if (m > SEL_MAX) m = SEL_MAX;
    int i = blockIdx.x * blockDim.x + threadIdx.x;
    if (i >= m) return;
    int r = g_rank[i];
    if (r >= K_TOP) return;
    unsigned long long key = g_sel[i];
    unsigned idx = 0xFFFFFFFFu - (unsigned)(key & 0xFFFFFFFFull);
    float val = __uint_as_float((unsigned)(key >> 32));
    int bi = (int)(idx / C_CLS);
    int lb = (int)(idx % C_CLS);
    float x1 = fminf(fmaxf(boxes[bi * 4 + 0], 0.0f), IMG_W - 1.0f);
    float y1 = fminf(fmaxf(boxes[bi * 4 + 1], 0.0f), IMG_H - 1.0f);
    float x2 = fminf(fmaxf(boxes[bi * 4 + 2], 0.0f), IMG_W - 1.0f);
    float y2 = fminf(fmaxf(boxes[bi * 4 + 3], 0.0f), IMG_H - 1.0f);
    g_bk[r][0] = x1; g_bk[r][1] = y1; g_bk[r][2] = x2; g_bk[r][3] = y2;
    g_val[r] = val; g_label[r] = lb;
    float off = __fmul_rn((float)lb, CLS_OFF);
    float ox1 = __fadd_rn(x1, off), oy1 = __fadd_rn(y1, off);
    float ox2 = __fadd_rn(x2, off), oy2 = __fadd_rn(y2, off);
    g_boff[r][0] = ox1; g_boff[r][1] = oy1; g_boff[r][2] = ox2; g_boff[r][3] = oy2;
    g_area[r] = __fmul_rn(__fsub_rn(ox2, ox1), __fsub_rn(oy2, oy1));
    int p = atomicAdd(&g_clsCnt[lb], 1);
    if (p < NMS_CAP) g_clsRows[lb * NMS_CAP + p] = r;
}

// Per-class NMS: one warp per class (cross-class IoU provably 0 due to the
// 4096-px class offset). Rows come from the per-class list (arbitrary order),
// get ordered by rank via O(k^2/32) counting sort, then greedy chain.
__global__ void k_nms() {
    __shared__ int s_r[NMS_CAP];
    __shared__ int s_rows[NMS_CAP];
    __shared__ float s_box[NMS_CAP][4];
    __shared__ float s_area[NMS_CAP];
    __shared__ unsigned long long s_sup[NMS_CAP][4];
    __shared__ unsigned long long s_rm[4];

    int c = blockIdx.x + 1;          // classes 1..80
    int lane = threadIdx.x;          // 32 threads

    int k = g_clsCnt[c];
    if (lane == 0) g_clsCnt[c] = 0;  // consume-then-reset (before any early exit)
    if (k > NMS_CAP) k = NMS_CAP;
    if (k <= 1) return;

    for (int i = lane; i < k; i += 32) s_r[i] = g_clsRows[c * NMS_CAP + i];
    __syncwarp();

    // order ascending by rank (ranks unique): counting sort
    for (int i = lane; i < k; i += 32) {
        int ri = s_r[i];
        int pos = 0;
        for (int j = 0; j < k; j++) pos += (s_r[j] < ri);
        s_rows[pos] = ri;
    }
    __syncwarp();

    for (int i = lane; i < k; i += 32) {
        int r = s_rows[i];
        s_box[i][0] = g_boff[r][0]; s_box[i][1] = g_boff[r][1];
        s_box[i][2] = g_boff[r][2]; s_box[i][3] = g_boff[r][3];
        s_area[i] = g_area[r];
    }
    __syncwarp();

    // suppression rows: sup[i] bits j>i with IoU>0.5 (identical _rn sequence)
    for (int i = lane; i < k; i += 32) {
        float x1 = s_box[i][0], y1 = s_box[i][1], x2 = s_box[i][2], y2 = s_box[i][3];
        float ai = s_area[i];
        unsigned long long w0 = 0, w1 = 0, w2 = 0, w3 = 0;
        for (int j = i + 1; j < k; j++) {
            float iw = fmaxf(__fsub_rn(fminf(x2, s_box[j][2]), fmaxf(x1, s_box[j][0])), 0.0f);
            float ih = fmaxf(__fsub_rn(fminf(y2, s_box[j][3]), fmaxf(y1, s_box[j][1])), 0.0f);
            float inter = __fmul_rn(iw, ih);
            float denom = __fadd_rn(__fsub_rn(__fadd_rn(ai, s_area[j]), inter), 1e-9f);
            if (__fdiv_rn(inter, denom) > NMS_T) {
                unsigned long long b = 1ull << (j & 63);
                switch (j >> 6) { case 0: w0 |= b; break; case 1: w1 |= b; break;
                                  case 2: w2 |= b; break; default: w3 |= b; break; }
            }
        }
        s_sup[i][0] = w0; s_sup[i][1] = w1; s_sup[i][2] = w2; s_sup[i][3] = w3;
    }
    __syncwarp();

    if (lane == 0) {
        unsigned long long r0 = 0, r1 = 0, r2 = 0, r3 = 0;
        for (int i = 0; i < k; i++) {
            unsigned long long rw = (i < 64) ? r0 : (i < 128) ? r1 : (i < 192) ? r2 : r3;
            if (!((rw >> (i & 63)) & 1ull)) {
                r0 |= s_sup[i][0]; r1 |= s_sup[i][1];
                r2 |= s_sup[i][2]; r3 |= s_sup[i][3];
            }
        }
        s_rm[0] = r0; s_rm[1] = r1; s_rm[2] = r2; s_rm[3] = r3;
    }
    __syncwarp();

    if (lane < 4) {
        unsigned long long bits = s_rm[lane];
        while (bits) {
            int b = __ffsll((long long)bits) - 1;
            bits &= bits - 1ull;
            int li = lane * 64 + b;
            if (li < k) {
                int r = s_rows[li];
                atomicOr(&g_removed[r >> 6], 1ull << (r & 63));
            }
        }
    }
}

// single block: snapshot g_removed, reset it (for the next call), emit output
// layout (float32, concatenated): dets[4096*5], labels[4096], keep[4096]
__global__ void k_out(float* __restrict__ out, int out_size) {
    __shared__ unsigned long long s_rm[64];
    int t = threadIdx.x;
    if (t < 64) s_rm[t] = g_removed[t];
    __syncthreads();
    if (t < 64) g_removed[t] = 0ull;

    for (int o = t; o < out_size; o += blockDim.x) {
        float v = 0.0f;
        if (o < K_TOP * 5) {
            int r = o / 5, c = o - r * 5;
            bool keep = !((s_rm[r >> 6] >> (r & 63)) & 1ull) && (g_val[r] > 0.0f);
            if (keep) v = (c < 4) ? g_bk[r][c] : g_val[r];
        } else if (o < K_TOP * 6) {
            v = (float)g_label[o - K_TOP * 5];
        } else if (o < K_TOP * 7) {
            int r = o - K_TOP * 6;
            bool keep = !((s_rm[r >> 6] >> (r & 63)) & 1ull) && (g_val[r] > 0.0f);
            v = keep ? 1.0f : 0.0f;
        }
        out[o] = v;
    }
}

extern "C" void kernel_launch(void* const* d_in, const int* in_sizes, int n_in,
                              void* d_out, int out_size) {
    const float* x     = (const float*)d_in[0];
    const float* boxes = (const float*)d_in[1];
    float* out = (float*)d_out;

    k_softmax<<<N_BOX / 8, 256>>>(x);
    k_findcut<<<1, 1024>>>();
    k_compact<<<512, 256>>>();
    dim3 gr(SEL_MAX / 256, SEL_MAX / 256);
    k_rank<<<gr, 256>>>();
    k_scatter<<<SEL_MAX / 256, 256>>>(boxes);
    k_nms<<<C_CLS - 1, 32>>>();
    k_out<<<1, 1024>>>(out, out_size);
}

// round 13
// speedup vs baseline: 1.5459x; 1.1204x over previous
#include <cuda_runtime.h>
#include <stdint.h>

#define N_BOX 32768
#define C_CLS 81
#define K_TOP 4096
#define SCORE_T 0.05f
#define NMS_T 0.5f
#define IMG_W 1333.0f
#define IMG_H 800.0f
#define CLS_OFF 4096.0f

// p in (0.05, 1.0]  =>  float top-16 bits in [0x3D4C, 0x3F80]
#define HIST_LO 0x3D4C
#define HIST_N  565
#define BKT_CAP 2048     // max keys per 16-bit bucket (worst observed ~400)

#define NMS_CAP 256      // max rows per class (mean ~51)

// ---- device state. Invariant: every counter is zero on entry to each call
// (zero-init at load; consume-then-reset within each call thereafter).
__device__ unsigned int g_bktCnt[HIST_N];
__device__ unsigned long long g_bktKeys[HIST_N * BKT_CAP];   // 9.3 MB scratch
__device__ int g_cutBucket;
__device__ int g_base[HIST_N];     // keys in buckets strictly above b

__device__ int g_clsCnt[C_CLS];
__device__ int g_clsRows[C_CLS * NMS_CAP];

__device__ float g_bk[K_TOP][4];
__device__ float g_boff[K_TOP][4];
__device__ float g_area[K_TOP];
__device__ float g_val[K_TOP];
__device__ int   g_label[K_TOP];

__device__ unsigned long long g_removed[64];

// xor-butterfly tree sum — all lanes end with identical bits (VALIDATED)
__device__ __forceinline__ float btree_add(float v) {
    #pragma unroll
    for (int o = 16; o; o >>= 1) v = __fadd_rn(v, __shfl_xor_sync(0xFFFFFFFFu, v, o));
    return v;
}

__device__ __forceinline__ void emit_cand(unsigned vb, unsigned idx) {
    int b = (int)(vb >> 16) - HIST_LO;
    unsigned pos = atomicAdd(&g_bktCnt[b], 1u);
    if (pos < BKT_CAP)
        g_bktKeys[b * BKT_CAP + pos] =
            ((unsigned long long)vb << 32) | (0xFFFFFFFFu - idx);
}

// one warp per row — bitwise model of the Triton/MLIR normalization emitter
// (VALIDATED round 6: rel_err 9.3e-12 — arithmetic is FROZEN; only the
// candidate routing changed: direct per-bucket store, order-free)
__global__ void k_softmax(const float* __restrict__ x) {
    int warp = (blockIdx.x * blockDim.x + threadIdx.x) >> 5;
    int lane = threadIdx.x & 31;
    if (warp >= N_BOX) return;
    const float* row = x + (size_t)warp * C_CLS;

    float v0 = row[lane];
    float v1 = row[lane + 32];
    float v2 = (lane < 17) ? row[lane + 64] : -1e30f;

    float m = fmaxf(fmaxf(v0, v1), v2);
    #pragma unroll
    for (int o = 16; o; o >>= 1) m = fmaxf(m, __shfl_xor_sync(0xFFFFFFFFu, m, o));

    float e0 = expf(__fsub_rn(v0, m));
    float e1 = expf(__fsub_rn(v1, m));
    float e2 = (lane < 17) ? expf(__fsub_rn(v2, m)) : 0.0f;

    float B0 = btree_add(e0);
    float B1 = btree_add(e1);
    float B2 = btree_add(e2);
    float s = __fadd_rn(__fadd_rn(B0, B2), B1);

    float p0 = __fdiv_rn(e0, s);
    float p1 = __fdiv_rn(e1, s);
    float p2 = __fdiv_rn(e2, s);

    unsigned rowbase = (unsigned)warp * C_CLS;
    if ((lane != 0) && (p0 > SCORE_T)) emit_cand(__float_as_uint(p0), rowbase + lane);
    if (p1 > SCORE_T)                  emit_cand(__float_as_uint(p1), rowbase + lane + 32);
    if ((lane < 17) && (p2 > SCORE_T)) emit_cand(__float_as_uint(p2), rowbase + lane + 64);
}

// suffix bases from the bucket counters (== histogram); find cut bucket.
// Does NOT reset g_bktCnt — k_rankscatter consumes then resets it.
__global__ void k_findcut() {
    __shared__ unsigned int h[HIST_N];
    int t = threadIdx.x;
    if (t < HIST_N) h[t] = g_bktCnt[t];
    __syncthreads();
    if (t == 0) {
        unsigned int acc = 0;
        int b = HIST_N - 1;
        int cut = 0;
        for (; b >= 0; b--) {
            g_base[b] = (int)acc;
            unsigned c = h[b]; if (c > BKT_CAP) c = BKT_CAP;
            acc += c;
            if (acc >= K_TOP) { cut = b; break; }
        }
        g_cutBucket = cut;
    }
}

// one CTA per bucket: exact local rank within bucket (keys unique, shared
// 16-bit prefix), global rank = base[b] + local; decode straight into the
// final sorted slot; build per-class lists.
// Consume-then-reset of g_bktCnt is race-safe: ALL threads read kb, then a
// full __syncthreads(), and only then does t0 reset — before any early return.
__global__ void k_rankscatter(const float* __restrict__ boxes) {
    __shared__ unsigned long long keys[BKT_CAP];
    int b = blockIdx.x;
    int t = threadIdx.x;
    int kb = (int)g_bktCnt[b];
    __syncthreads();                 // every thread has read kb
    if (t == 0) g_bktCnt[b] = 0u;    // safe reset (R12 bug: this preceded the barrier)
    if (kb > BKT_CAP) kb = BKT_CAP;
    if (kb == 0 || b < g_cutBucket) return;
    int base = g_base[b];

    for (int i = t; i < kb; i += blockDim.x) keys[i] = g_bktKeys[b * BKT_CAP + i];
    __syncthreads();

    for (int i = t; i < kb; i += blockDim.x) {
        unsigned long long key = keys[i];
        int lr = 0;
        for (int j = 0; j < kb; j++) lr += (keys[j] > key);
        int r = base + lr;
        if (r >= K_TOP) continue;
        unsigned idx = 0xFFFFFFFFu - (unsigned)(key & 0xFFFFFFFFull);
        float val = __uint_as_float((unsigned)(key >> 32));
        int bi = (int)(idx / C_CLS);
        int lb = (int)(idx % C_CLS);
        float x1 = fminf(fmaxf(boxes[bi * 4 + 0], 0.0f), IMG_W - 1.0f);
        float y1 = fminf(fmaxf(boxes[bi * 4 + 1], 0.0f), IMG_H - 1.0f);
        float x2 = fminf(fmaxf(boxes[bi * 4 + 2], 0.0f), IMG_W - 1.0f);
        float y2 = fminf(fmaxf(boxes[bi * 4 + 3], 0.0f), IMG_H - 1.0f);
        g_bk[r][0] = x1; g_bk[r][1] = y1; g_bk[r][2] = x2; g_bk[r][3] = y2;
        g_val[r] = val; g_label[r] = lb;
        float off = __fmul_rn((float)lb, CLS_OFF);
        float ox1 = __fadd_rn(x1, off), oy1 = __fadd_rn(y1, off);
        float ox2 = __fadd_rn(x2, off), oy2 = __fadd_rn(y2, off);
        g_boff[r][0] = ox1; g_boff[r][1] = oy1; g_boff[r][2] = ox2; g_boff[r][3] = oy2;
        g_area[r] = __fmul_rn(__fsub_rn(ox2, ox1), __fsub_rn(oy2, oy1));
        int p = atomicAdd(&g_clsCnt[lb], 1);
        if (p < NMS_CAP) g_clsRows[lb * NMS_CAP + p] = r;
    }
}

// Per-class NMS: one warp per class (cross-class IoU provably 0 due to the
// 4096-px class offset). Orders rows by rank (counting sort), computes the
// per-class suppression matrix, runs the greedy chain. Resets g_clsCnt
// (safe: single warp — all lanes read k in the same instruction before the
// lane-0 store).
__global__ void k_nms() {
    __shared__ int s_r[NMS_CAP];
    __shared__ int s_rows[NMS_CAP];
    __shared__ float s_box[NMS_CAP][4];
    __shared__ float s_area[NMS_CAP];
    __shared__ unsigned long long s_sup[NMS_CAP][4];
    __shared__ unsigned long long s_rm[4];

    int c = blockIdx.x + 1;          // classes 1..80
    int lane = threadIdx.x;          // 32 threads

    int k = g_clsCnt[c];
    __syncwarp();
    if (lane == 0) g_clsCnt[c] = 0;  // consume-then-reset before any early exit
    if (k > NMS_CAP) k = NMS_CAP;
    if (k <= 1) return;

    for (int i = lane; i < k; i += 32) s_r[i] = g_clsRows[c * NMS_CAP + i];
    __syncwarp();

    // order ascending by rank (ranks unique): counting sort
    for (int i = lane; i < k; i += 32) {
        int ri = s_r[i];
        int pos = 0;
        for (int j = 0; j < k; j++) pos += (s_r[j] < ri);
        s_rows[pos] = ri;
    }
    __syncwarp();

    for (int i = lane; i < k; i += 32) {
        int r = s_rows[i];
        s_box[i][0] = g_boff[r][0]; s_box[i][1] = g_boff[r][1];
        s_box[i][2] = g_boff[r][2]; s_box[i][3] = g_boff[r][3];
        s_area[i] = g_area[r];
    }
    __syncwarp();

    // suppression rows: sup[i] bits j>i with IoU>0.5 (identical _rn sequence)
    for (int i = lane; i < k; i += 32) {
        float x1 = s_box[i][0], y1 = s_box[i][1], x2 = s_box[i][2], y2 = s_box[i][3];
        float ai = s_area[i];
        unsigned long long w0 = 0, w1 = 0, w2 = 0, w3 = 0;
        for (int j = i + 1; j < k; j++) {
            float iw = fmaxf(__fsub_rn(fminf(x2, s_box[j][2]), fmaxf(x1, s_box[j][0])), 0.0f);
            float ih = fmaxf(__fsub_rn(fminf(y2, s_box[j][3]), fmaxf(y1, s_box[j][1])), 0.0f);
            float inter = __fmul_rn(iw, ih);
            float denom = __fadd_rn(__fsub_rn(__fadd_rn(ai, s_area[j]), inter), 1e-9f);
            if (__fdiv_rn(inter, denom) > NMS_T) {
                unsigned long long bb = 1ull << (j & 63);
                switch (j >> 6) { case 0: w0 |= bb; break; case 1: w1 |= bb; break;
                                  case 2: w2 |= bb; break; default: w3 |= bb; break; }
            }
        }
        s_sup[i][0] = w0; s_sup[i][1] = w1; s_sup[i][2] = w2; s_sup[i][3] = w3;
    }
    __syncwarp();

    if (lane == 0) {
        unsigned long long r0 = 0, r1 = 0, r2 = 0, r3 = 0;
        for (int i = 0; i < k; i++) {
            unsigned long long rw = (i < 64) ? r0 : (i < 128) ? r1 : (i < 192) ? r2 : r3;
            if (!((rw >> (i & 63)) & 1ull)) {
                r0 |= s_sup[i][0]; r1 |= s_sup[i][1];
                r2 |= s_sup[i][2]; r3 |= s_sup[i][3];
            }
        }
        s_rm[0] = r0; s_rm[1] = r1; s_rm[2] = r2; s_rm[3] = r3;
    }
    __syncwarp();

    if (lane < 4) {
        unsigned long long bits = s_rm[lane];
        while (bits) {
            int bb = __ffsll((long long)bits) - 1;
            bits &= bits - 1ull;
            int li = lane * 64 + bb;
            if (li < k) {
                int r = s_rows[li];
                atomicOr(&g_removed[r >> 6], 1ull << (r & 63));
            }
        }
    }
}

// single block: snapshot g_removed, reset it (for the next call), emit output
// layout (float32, concatenated): dets[4096*5], labels[4096], keep[4096]
__global__ void k_out(float* __restrict__ out, int out_size) {
    __shared__ unsigned long long s_rm[64];
    int t = threadIdx.x;
    if (t < 64) s_rm[t] = g_removed[t];
    __syncthreads();
    if (t < 64) g_removed[t] = 0ull;

    for (int o = t; o < out_size; o += blockDim.x) {
        float v = 0.0f;
        if (o < K_TOP * 5) {
            int r = o / 5, c = o - r * 5;
            bool keep = !((s_rm[r >> 6] >> (r & 63)) & 1ull) && (g_val[r] > 0.0f);
            if (keep) v = (c < 4) ? g_bk[r][c] : g_val[r];
        } else if (o < K_TOP * 6) {
            v = (float)g_label[o - K_TOP * 5];
        } else if (o < K_TOP * 7) {
            int r = o - K_TOP * 6;
            bool keep = !((s_rm[r >> 6] >> (r & 63)) & 1ull) && (g_val[r] > 0.0f);
            v = keep ? 1.0f : 0.0f;
        }
        out[o] = v;
    }
}

extern "C" void kernel_launch(void* const* d_in, const int* in_sizes, int n_in,
                              void* d_out, int out_size) {
    const float* x     = (const float*)d_in[0];
    const float* boxes = (const float*)d_in[1];
    float* out = (float*)d_out;

    k_softmax<<<N_BOX / 8, 256>>>(x);
    k_findcut<<<1, 576>>>();
    k_rankscatter<<<HIST_N, 256>>>(boxes);
    k_nms<<<C_CLS - 1, 32>>>();
    k_out<<<1, 1024>>>(out, out_size);
}

// round 14
// speedup vs baseline: 1.9412x; 1.2557x over previous
#include <cuda_runtime.h>
#include <stdint.h>

#define N_BOX 32768
#define C_CLS 81
#define K_TOP 4096
#define SCORE_T 0.05f
#define NMS_T 0.5f
#define IMG_W 1333.0f
#define IMG_H 800.0f
#define CLS_OFF 4096.0f

// p in (0.05, 1.0]  =>  float top-16 bits in [0x3D4C, 0x3F80]
#define HIST_LO 0x3D4C
#define HIST_N  565
#define BKT_CAP 2048     // max keys per 16-bit bucket (worst observed ~400)

#define NMS_CAP 256      // max rows per class (mean ~51)

// ---- device state. Invariant: every counter is zero on entry to each call
// (zero-init at load; consume-then-reset within each call thereafter).
__device__ unsigned int g_bktCnt[HIST_N];
__device__ unsigned long long g_bktKeys[HIST_N * BKT_CAP];   // 9.3 MB scratch
__device__ int g_cutBucket;
__device__ int g_base[HIST_N];     // keys in buckets strictly above b

__device__ int g_clsCnt[C_CLS];
__device__ int g_clsRows[C_CLS * NMS_CAP];

__device__ float g_bk[K_TOP][4];
__device__ float g_boff[K_TOP][4];
__device__ float g_area[K_TOP];
__device__ float g_val[K_TOP];
__device__ int   g_label[K_TOP];

__device__ unsigned long long g_removed[64];

// xor-butterfly tree sum — all lanes end with identical bits (VALIDATED)
__device__ __forceinline__ float btree_add(float v) {
    #pragma unroll
    for (int o = 16; o; o >>= 1) v = __fadd_rn(v, __shfl_xor_sync(0xFFFFFFFFu, v, o));
    return v;
}

__device__ __forceinline__ void emit_cand(unsigned vb, unsigned idx) {
    int b = (int)(vb >> 16) - HIST_LO;
    unsigned pos = atomicAdd(&g_bktCnt[b], 1u);
    if (pos < BKT_CAP)
        g_bktKeys[b * BKT_CAP + pos] =
            ((unsigned long long)vb << 32) | (0xFFFFFFFFu - idx);
}

// one warp per row — bitwise model of the Triton/MLIR normalization emitter
// (VALIDATED round 6: rel_err 9.3e-12 — arithmetic is FROZEN)
__global__ void k_softmax(const float* __restrict__ x) {
    int warp = (blockIdx.x * blockDim.x + threadIdx.x) >> 5;
    int lane = threadIdx.x & 31;
    if (warp >= N_BOX) return;
    const float* row = x + (size_t)warp * C_CLS;

    float v0 = row[lane];
    float v1 = row[lane + 32];
    float v2 = (lane < 17) ? row[lane + 64] : -1e30f;

    float m = fmaxf(fmaxf(v0, v1), v2);
    #pragma unroll
    for (int o = 16; o; o >>= 1) m = fmaxf(m, __shfl_xor_sync(0xFFFFFFFFu, m, o));

    float e0 = expf(__fsub_rn(v0, m));
    float e1 = expf(__fsub_rn(v1, m));
    float e2 = (lane < 17) ? expf(__fsub_rn(v2, m)) : 0.0f;

    float B0 = btree_add(e0);
    float B1 = btree_add(e1);
    float B2 = btree_add(e2);
    float s = __fadd_rn(__fadd_rn(B0, B2), B1);

    float p0 = __fdiv_rn(e0, s);
    float p1 = __fdiv_rn(e1, s);
    float p2 = __fdiv_rn(e2, s);

    unsigned rowbase = (unsigned)warp * C_CLS;
    if ((lane != 0) && (p0 > SCORE_T)) emit_cand(__float_as_uint(p0), rowbase + lane);
    if (p1 > SCORE_T)                  emit_cand(__float_as_uint(p1), rowbase + lane + 32);
    if ((lane < 17) && (p2 > SCORE_T)) emit_cand(__float_as_uint(p2), rowbase + lane + 64);
}

// suffix bases from the bucket counters (== histogram); find cut bucket.
// Does NOT reset g_bktCnt — k_rankscatter consumes then resets it.
__global__ void k_findcut() {
    __shared__ unsigned int h[HIST_N];
    int t = threadIdx.x;
    if (t < HIST_N) h[t] = g_bktCnt[t];
    __syncthreads();
    if (t == 0) {
        unsigned int acc = 0;
        int b = HIST_N - 1;
        int cut = 0;
        for (; b >= 0; b--) {
            g_base[b] = (int)acc;
            unsigned c = h[b]; if (c > BKT_CAP) c = BKT_CAP;
            acc += c;
            if (acc >= K_TOP) { cut = b; break; }
        }
        g_cutBucket = cut;
    }
}

// one CTA per bucket: exact local rank within bucket (keys unique, shared
// 16-bit prefix), global rank = base[b] + local; decode straight into the
// final sorted slot; build per-class lists.
// Consume-then-reset is race-safe: all threads read kb, __syncthreads, then
// t0 resets — before any early return.
__global__ void k_rankscatter(const float* __restrict__ boxes) {
    __shared__ unsigned long long keys[BKT_CAP];
    int b = blockIdx.x;
    int t = threadIdx.x;
    int kb = (int)g_bktCnt[b];
    __syncthreads();
    if (t == 0) g_bktCnt[b] = 0u;
    if (kb > BKT_CAP) kb = BKT_CAP;
    if (kb == 0 || b < g_cutBucket) return;
    int base = g_base[b];

    for (int i = t; i < kb; i += blockDim.x) keys[i] = g_bktKeys[b * BKT_CAP + i];
    __syncthreads();

    for (int i = t; i < kb; i += blockDim.x) {
        unsigned long long key = keys[i];
        int lr = 0;
        for (int j = 0; j < kb; j++) lr += (keys[j] > key);
        int r = base + lr;
        if (r >= K_TOP) continue;
        unsigned idx = 0xFFFFFFFFu - (unsigned)(key & 0xFFFFFFFFull);
        float val = __uint_as_float((unsigned)(key >> 32));
        int bi = (int)(idx / C_CLS);
        int lb = (int)(idx % C_CLS);
        float x1 = fminf(fmaxf(boxes[bi * 4 + 0], 0.0f), IMG_W - 1.0f);
        float y1 = fminf(fmaxf(boxes[bi * 4 + 1], 0.0f), IMG_H - 1.0f);
        float x2 = fminf(fmaxf(boxes[bi * 4 + 2], 0.0f), IMG_W - 1.0f);
        float y2 = fminf(fmaxf(boxes[bi * 4 + 3], 0.0f), IMG_H - 1.0f);
        g_bk[r][0] = x1; g_bk[r][1] = y1; g_bk[r][2] = x2; g_bk[r][3] = y2;
        g_val[r] = val; g_label[r] = lb;
        float off = __fmul_rn((float)lb, CLS_OFF);
        float ox1 = __fadd_rn(x1, off), oy1 = __fadd_rn(y1, off);
        float ox2 = __fadd_rn(x2, off), oy2 = __fadd_rn(y2, off);
        g_boff[r][0] = ox1; g_boff[r][1] = oy1; g_boff[r][2] = ox2; g_boff[r][3] = oy2;
        g_area[r] = __fmul_rn(__fsub_rn(ox2, ox1), __fsub_rn(oy2, oy1));
        int p = atomicAdd(&g_clsCnt[lb], 1);
        if (p < NMS_CAP) g_clsRows[lb * NMS_CAP + p] = r;
    }
}

// Per-class NMS: one 256-thread block per class (8 warps — hides LDS/FDIV
// latency that killed the 32-thread version). Cross-class IoU is provably 0
// (4096-px class offset). One thread per row; division only when inter > 0
// (bit-exact: inter==0 => iou==0 exactly => no suppression).
__global__ void k_nms() {
    __shared__ int s_r[NMS_CAP];
    __shared__ int s_rows[NMS_CAP];
    __shared__ float s_box[NMS_CAP][4];
    __shared__ float s_area[NMS_CAP];
    __shared__ unsigned long long s_sup[NMS_CAP][4];
    __shared__ unsigned long long s_rm[4];

    int c = blockIdx.x + 1;          // classes 1..80
    int t = threadIdx.x;             // 256 threads

    int k = g_clsCnt[c];
    __syncthreads();                 // all threads read k
    if (t == 0) g_clsCnt[c] = 0;     // consume-then-reset (uniform k => uniform return)
    if (k > NMS_CAP) k = NMS_CAP;
    if (k <= 1) return;

    if (t < k) s_r[t] = g_clsRows[c * NMS_CAP + t];
    __syncthreads();

    // order ascending by rank (ranks unique): counting sort, one thread/row
    if (t < k) {
        int ri = s_r[t];
        int pos = 0;
        for (int j = 0; j < k; j++) pos += (s_r[j] < ri);
        s_rows[pos] = ri;
    }
    __syncthreads();

    if (t < k) {
        int r = s_rows[t];
        s_box[t][0] = g_boff[r][0]; s_box[t][1] = g_boff[r][1];
        s_box[t][2] = g_boff[r][2]; s_box[t][3] = g_boff[r][3];
        s_area[t] = g_area[r];
    }
    __syncthreads();

    // suppression rows: sup[i] bits j>i with IoU>0.5 (identical _rn sequence;
    // division skipped when inter==0 — outcome provably identical)
    if (t < k) {
        int i = t;
        float x1 = s_box[i][0], y1 = s_box[i][1], x2 = s_box[i][2], y2 = s_box[i][3];
        float ai = s_area[i];
        unsigned long long w0 = 0, w1 = 0, w2 = 0, w3 = 0;
        for (int j = i + 1; j < k; j++) {
            float iw = fmaxf(__fsub_rn(fminf(x2, s_box[j][2]), fmaxf(x1, s_box[j][0])), 0.0f);
            float ih = fmaxf(__fsub_rn(fminf(y2, s_box[j][3]), fmaxf(y1, s_box[j][1])), 0.0f);
            float inter = __fmul_rn(iw, ih);
            if (inter > 0.0f) {
                float denom = __fadd_rn(__fsub_rn(__fadd_rn(ai, s_area[j]), inter), 1e-9f);
                if (__fdiv_rn(inter, denom) > NMS_T) {
                    unsigned long long bb = 1ull << (j & 63);
                    switch (j >> 6) { case 0: w0 |= bb; break; case 1: w1 |= bb; break;
                                      case 2: w2 |= bb; break; default: w3 |= bb; break; }
                }
            }
        }
        s_sup[i][0] = w0; s_sup[i][1] = w1; s_sup[i][2] = w2; s_sup[i][3] = w3;
    }
    __syncthreads();

    // serial greedy chain (thread 0); k iterations over smem
    if (t == 0) {
        unsigned long long r0 = 0, r1 = 0, r2 = 0, r3 = 0;
        for (int i = 0; i < k; i++) {
            unsigned long long rw = (i < 64) ? r0 : (i < 128) ? r1 : (i < 192) ? r2 : r3;
            if (!((rw >> (i & 63)) & 1ull)) {
                r0 |= s_sup[i][0]; r1 |= s_sup[i][1];
                r2 |= s_sup[i][2]; r3 |= s_sup[i][3];
            }
        }
        s_rm[0] = r0; s_rm[1] = r1; s_rm[2] = r2; s_rm[3] = r3;
    }
    __syncthreads();

    if (t < 4) {
        unsigned long long bits = s_rm[t];
        while (bits) {
            int bb = __ffsll((long long)bits) - 1;
            bits &= bits - 1ull;
            int li = t * 64 + bb;
            if (li < k) {
                int r = s_rows[li];
                atomicOr(&g_removed[r >> 6], 1ull << (r & 63));
            }
        }
    }
}

// single block: snapshot g_removed, reset it (for the next call), emit output
// layout (float32, concatenated): dets[4096*5], labels[4096], keep[4096]
__global__ void k_out(float* __restrict__ out, int out_size) {
    __shared__ unsigned long long s_rm[64];
    int t = threadIdx.x;
    if (t < 64) s_rm[t] = g_removed[t];
    __syncthreads();
    if (t < 64) g_removed[t] = 0ull;

    for (int o = t; o < out_size; o += blockDim.x) {
        float v = 0.0f;
        if (o < K_TOP * 5) {
            int r = o / 5, c = o - r * 5;
            bool keep = !((s_rm[r >> 6] >> (r & 63)) & 1ull) && (g_val[r] > 0.0f);
            if (keep) v = (c < 4) ? g_bk[r][c] : g_val[r];
        } else if (o < K_TOP * 6) {
            v = (float)g_label[o - K_TOP * 5];
        } else if (o < K_TOP * 7) {
            int r = o - K_TOP * 6;
            bool keep = !((s_rm[r >> 6] >> (r & 63)) & 1ull) && (g_val[r] > 0.0f);
            v = keep ? 1.0f : 0.0f;
        }
        out[o] = v;
    }
}

extern "C" void kernel_launch(void* const* d_in, const int* in_sizes, int n_in,
                              void* d_out, int out_size) {
    const float* x     = (const float*)d_in[0];
    const float* boxes = (const float*)d_in[1];
    float* out = (float*)d_out;

    k_softmax<<<N_BOX / 8, 256>>>(x);
    k_findcut<<<1, 576>>>();
    k_rankscatter<<<HIST_N, 256>>>(boxes);
    k_nms<<<C_CLS - 1, 256>>>();
    k_out<<<1, 1024>>>(out, out_size);
}